// round 16
// baseline (speedup 1.0000x reference)
#include <cuda_runtime.h>
#include <cuda_bf16.h>
#include <cuda_fp16.h>
#include <cstdint>
#include <math.h>

// ---------------------------------------------------------------------------
// ACM-GCN on GB300, round 16 = round 15 + ticket-based CSR scatter:
//  the deg atomic's return value IS the within-row slot; store it per edge
//  (ticket[]) and scatter becomes atomic-free (rowptr[r] + ticket[e]).
//  Removes 1.6M L2 atomics from scatter_kernel and deletes the fill array.
// ---------------------------------------------------------------------------

#define MAXN 100000
#define MAXE 1600000

__device__ int   g_deg[MAXN];
__device__ int   g_rowptr[MAXN + 1];
__device__ int   g_col[MAXE];
__device__ int   g_ticket[MAXE];
__device__ __half g_x16[(size_t)MAXN * 128];
__device__ __half g_agg16[(size_t)MAXN * 128];
__device__ __half g_dif16[(size_t)MAXN * 128];
__device__ __half g_hl16[(size_t)MAXN * 128];
__device__ __half g_hh16[(size_t)MAXN * 128];
__device__ __half g_hmm16[(size_t)MAXN * 128];
__device__ __half g_fea16[(size_t)MAXN * 128];
__device__ __half g_lh16[(size_t)MAXN * 128];
__device__ __half g_hm16[(size_t)MAXN * 64];
__device__ __half g_w1hi[3 * 128 * 128];
__device__ __half g_w1lo[3 * 128 * 128];
__device__ __half g_w2hi[3 * 64 * 128];
__device__ __half g_w2lo[3 * 64 * 128];

__device__ __forceinline__ uint32_t smem_u32(const void* p) {
    uint32_t a;
    asm("{ .reg .u64 t; cvta.to.shared.u64 t, %1; cvt.u32.u64 %0, t; }"
        : "=r"(a) : "l"(p));
    return a;
}

#define CP_ASYNC16(dst, src, sz) \
    asm volatile("cp.async.cg.shared.global [%0], [%1], 16, %2;" \
                 :: "r"(dst), "l"(src), "r"(sz))
#define CP_COMMIT() asm volatile("cp.async.commit_group;" ::: "memory")
#define CP_WAIT1()  asm volatile("cp.async.wait_group 1;" ::: "memory")

// --------------------------- CSR construction -----------------------------

__global__ void zero_kernel(int* deg, int n) {
    int i = blockIdx.x * blockDim.x + threadIdx.x;
    if (i < n) deg[i] = 0;
}

// fused: deg atomics (+ticket) + x16 convert + W1/W2 split converts
__global__ void work_kernel(const int* __restrict__ row, int* deg, int* __restrict__ ticket,
                            int E,
                            const float* __restrict__ x, __half* __restrict__ x16,
                            const float* __restrict__ W0a, const float* __restrict__ W1a,
                            const float* __restrict__ W2a,
                            __half* __restrict__ w1hi, __half* __restrict__ w1lo,
                            const float* __restrict__ W0b, const float* __restrict__ W1b,
                            const float* __restrict__ W2b,
                            __half* __restrict__ w2hi, __half* __restrict__ w2lo,
                            int n) {
    const int xcnt = n * 32;
    const int w1cnt = 3 * 128 * 128;
    const int w2cnt = 3 * 64 * 128;
    int id = blockIdx.x * blockDim.x + threadIdx.x;

    if (id < E) {
        ticket[id] = atomicAdd(&deg[row[id]], 1);
        return;
    }
    id -= E;
    if (id < xcnt) {
        float4 v = ((const float4*)x)[id];
        __half2 p0 = __floats2half2_rn(v.x, v.y);
        __half2 p1 = __floats2half2_rn(v.z, v.w);
        uint2 o;
        o.x = *(uint32_t*)&p0; o.y = *(uint32_t*)&p1;
        ((uint2*)x16)[id] = o;
        return;
    }
    id -= xcnt;
    if (id < w1cnt) {
        const int K = 128, Nn = 128;
        int y = id / (K * Nn);
        int rem = id - y * K * Nn;
        int k = rem / Nn;
        int nn = rem - k * Nn;
        const float* W = (y == 0) ? W0a : (y == 1) ? W1a : W2a;
        float w = W[k * Nn + nn];
        __half h = __float2half_rn(w);
        __half l = __float2half_rn(w - __half2float(h));
        w1hi[(size_t)y * Nn * K + nn * K + k] = h;
        w1lo[(size_t)y * Nn * K + nn * K + k] = l;
        return;
    }
    id -= w1cnt;
    if (id < w2cnt) {
        const int K = 128, Nn = 64;
        int y = id / (K * Nn);
        int rem = id - y * K * Nn;
        int k = rem / Nn;
        int nn = rem - k * Nn;
        const float* W = (y == 0) ? W0b : (y == 1) ? W1b : W2b;
        float w = W[k * Nn + nn];
        __half h = __float2half_rn(w);
        __half l = __float2half_rn(w - __half2float(h));
        w2hi[(size_t)y * Nn * K + nn * K + k] = h;
        w2lo[(size_t)y * Nn * K + nn * K + k] = l;
    }
}

__global__ void scan_kernel(const int* __restrict__ deg, int* __restrict__ rowptr, int n) {
    __shared__ int wsum[32];
    __shared__ int carry;
    int tid = threadIdx.x, lane = tid & 31, w = tid >> 5;
    if (tid == 0) carry = 0;
    __syncthreads();
    for (int base = 0; base < n; base += 1024) {
        int i = base + tid;
        int v = (i < n) ? deg[i] : 0;
        int x = v;
        #pragma unroll
        for (int o = 1; o < 32; o <<= 1) {
            int y = __shfl_up_sync(0xffffffffu, x, o);
            if (lane >= o) x += y;
        }
        if (lane == 31) wsum[w] = x;
        __syncthreads();
        if (w == 0) {
            int t = wsum[lane];
            #pragma unroll
            for (int o = 1; o < 32; o <<= 1) {
                int y = __shfl_up_sync(0xffffffffu, t, o);
                if (lane >= o) t += y;
            }
            wsum[lane] = t;
        }
        __syncthreads();
        int off = carry + (w > 0 ? wsum[w - 1] : 0);
        if (i < n) rowptr[i] = off + x - v;
        int blocktotal = wsum[31];
        __syncthreads();
        if (tid == 0) carry += blocktotal;
        __syncthreads();
    }
    if (threadIdx.x == 0) rowptr[n] = carry;
}

// atomic-free scatter via ticket
__global__ void scatter_kernel(const int* __restrict__ row, const int* __restrict__ colsrc,
                               const int* __restrict__ rowptr, const int* __restrict__ ticket,
                               int* __restrict__ colout, int E) {
    int e = blockIdx.x * blockDim.x + threadIdx.x;
    if (e < E) {
        int r = row[e];
        colout[rowptr[r] + ticket[e]] = colsrc[e];
    }
}

// -------------------- layer-1 spmm (fp16 gather, unroll8) ------------------

__global__ __launch_bounds__(256)
void spmm_cvt(const __half* __restrict__ x16,
              const int* __restrict__ rowptr, const int* __restrict__ col,
              __half* __restrict__ agg16, __half* __restrict__ dif16, int n) {
    int gw = (blockIdx.x * blockDim.x + threadIdx.x) >> 5;
    if (gw >= n) return;
    const int lane = threadIdx.x & 31;
    const int s = rowptr[gw], e = rowptr[gw + 1];

    float acc[4] = {0.f, 0.f, 0.f, 0.f};

    for (int base = s; base < e; base += 32) {
        int idx = base + lane;
        int c = (idx < e) ? col[idx] : 0;
        int cnt = min(32, e - base);
        int k = 0;
        for (; k + 8 <= cnt; k += 8) {
            uint2 v[8];
            #pragma unroll
            for (int j = 0; j < 8; j++) {
                int cc = __shfl_sync(0xffffffffu, c, k + j);
                v[j] = __ldg((const uint2*)(x16 + (size_t)cc * 128 + lane * 4));
            }
            #pragma unroll
            for (int j = 0; j < 8; j++) {
                float2 a = __half22float2(*(__half2*)&v[j].x);
                float2 b = __half22float2(*(__half2*)&v[j].y);
                acc[0] += a.x; acc[1] += a.y; acc[2] += b.x; acc[3] += b.y;
            }
        }
        for (; k < cnt; k++) {
            int cc = __shfl_sync(0xffffffffu, c, k);
            uint2 v = __ldg((const uint2*)(x16 + (size_t)cc * 128 + lane * 4));
            float2 a = __half22float2(*(__half2*)&v.x);
            float2 b = __half22float2(*(__half2*)&v.y);
            acc[0] += a.x; acc[1] += a.y; acc[2] += b.x; acc[3] += b.y;
        }
    }

    const float inv = (e > s) ? 1.0f / (float)(e - s) : 0.0f;
    uint2 ov = *(const uint2*)(x16 + (size_t)gw * 128 + lane * 4);
    float2 o01 = __half22float2(*(__half2*)&ov.x);
    float2 o23 = __half22float2(*(__half2*)&ov.y);
    float own[4] = {o01.x, o01.y, o23.x, o23.y};

    float agg[4], dif[4];
    #pragma unroll
    for (int i = 0; i < 4; i++) {
        agg[i] = inv * acc[i];
        dif[i] = own[i] - agg[i];
    }

    const size_t off = ((size_t)gw * 128 + lane * 4) / 4;
    __half2 a0 = __floats2half2_rn(agg[0], agg[1]);
    __half2 a1 = __floats2half2_rn(agg[2], agg[3]);
    __half2 d0 = __floats2half2_rn(dif[0], dif[1]);
    __half2 d1 = __floats2half2_rn(dif[2], dif[3]);
    uint2 av, dv;
    av.x = *(uint32_t*)&a0; av.y = *(uint32_t*)&a1;
    dv.x = *(uint32_t*)&d0; dv.y = *(uint32_t*)&d1;
    ((uint2*)agg16)[off] = av;
    ((uint2*)dif16)[off] = dv;
}

// ----------------------- fp16 2-product mma GEMMs --------------------------

#define MMA_F16(acc, af, b0, b1)                                              \
    asm volatile("mma.sync.aligned.m16n8k16.row.col.f32.f16.f16.f32 "         \
                 "{%0,%1,%2,%3}, {%4,%5,%6,%7}, {%8,%9}, {%0,%1,%2,%3};"      \
                 : "+f"((acc)[0]), "+f"((acc)[1]), "+f"((acc)[2]), "+f"((acc)[3]) \
                 : "r"((af)[0]), "r"((af)[1]), "r"((af)[2]), "r"((af)[3]),    \
                   "r"(b0), "r"(b1))

__device__ __forceinline__ void prefetchA(uint32_t bufAddr, const __half* A,
                                          int rowBase, int M, int tid, int SA) {
    #pragma unroll
    for (int i = tid; i < 128 * 16; i += 256) {
        int r = i >> 4, c = i & 15;
        int gr = rowBase + r;
        uint32_t dst = bufAddr + (uint32_t)((r * SA + c * 8) * 2);
        const __half* src = A + (size_t)gr * 128 + c * 8;
        int sz = (gr < M) ? 16 : 0;
        CP_ASYNC16(dst, src, sz);
    }
}

__global__ __launch_bounds__(256, 1)
void gemm_l1(const __half* __restrict__ A0, const __half* __restrict__ A1,
             const __half* __restrict__ A2,
             const __half* __restrict__ Whi, const __half* __restrict__ Wlo,
             __half* __restrict__ C0, __half* __restrict__ C1, __half* __restrict__ C2,
             int M) {
    constexpr int NB = 128, SA = 136, WN = 32, NT = 4, TILES = 4;
    extern __shared__ __align__(16) char smem[];
    __half* sA0 = (__half*)smem;
    __half* sA1 = sA0 + 128 * SA;
    __half* sBh = sA1 + 128 * SA;
    __half* sBl = sBh + NB * SA;

    const int tid = threadIdx.x, wid = tid >> 5, lane = tid & 31;
    const int y = blockIdx.y;
    const __half* A = (y == 0) ? A0 : (y == 1) ? A1 : A2;
    const __half* bh = Whi + (size_t)y * NB * 128;
    const __half* bl = Wlo + (size_t)y * NB * 128;
    __half* C = (y == 0) ? C0 : (y == 1) ? C1 : C2;

    #pragma unroll
    for (int i = tid; i < NB * 16; i += 256) {
        int r = i >> 4, c = i & 15;
        *(uint4*)(sBh + r * SA + c * 8) = *(const uint4*)(bh + r * 128 + c * 8);
        *(uint4*)(sBl + r * SA + c * 8) = *(const uint4*)(bl + r * 128 + c * 8);
    }

    const uint32_t aAddr[2] = { smem_u32(sA0), smem_u32(sA1) };
    const int tileBase = blockIdx.x * TILES;

    prefetchA(aAddr[0], A, tileBase * 128, M, tid, SA);
    CP_COMMIT();

    const int m0 = (wid >> 2) * 64;
    const int n0 = (wid & 3) * WN;
    const int aj = lane >> 3;
    const int aRow = ((aj & 1) << 3) + (lane & 7);
    const int aK = (aj >> 1) << 3;
    const int bRow = lane & 7;
    const int bK = ((lane >> 3) & 1) << 3;
    const uint32_t bhBase = smem_u32(sBh);
    const uint32_t blBase = smem_u32(sBl);

    #pragma unroll
    for (int t = 0; t < TILES; t++) {
        const int rowBase = (tileBase + t) * 128;
        if (rowBase >= M) break;

        const int nextBase = rowBase + 128;
        if (t + 1 < TILES && nextBase < M)
            prefetchA(aAddr[(t + 1) & 1], A, nextBase, M, tid, SA);
        CP_COMMIT();
        CP_WAIT1();
        __syncthreads();

        const uint32_t aBase = aAddr[t & 1];

        float acc[4][NT][4];
        #pragma unroll
        for (int mt = 0; mt < 4; mt++)
            #pragma unroll
            for (int nt = 0; nt < NT; nt++)
                #pragma unroll
                for (int j = 0; j < 4; j++) acc[mt][nt][j] = 0.0f;

        #pragma unroll
        for (int ks = 0; ks < 8; ks++) {
            const int k0 = ks * 16;
            uint32_t af[4][4];
            #pragma unroll
            for (int mt = 0; mt < 4; mt++) {
                uint32_t addr = aBase + (uint32_t)(((m0 + mt * 16 + aRow) * SA + k0 + aK) * 2);
                asm volatile("ldmatrix.sync.aligned.m8n8.x4.shared.b16 {%0,%1,%2,%3}, [%4];"
                             : "=r"(af[mt][0]), "=r"(af[mt][1]), "=r"(af[mt][2]), "=r"(af[mt][3])
                             : "r"(addr));
            }
            uint32_t bfh[NT][2], bfl[NT][2];
            #pragma unroll
            for (int nt = 0; nt < NT; nt++) {
                uint32_t boff = (uint32_t)(((n0 + nt * 8 + bRow) * SA + k0 + bK) * 2);
                asm volatile("ldmatrix.sync.aligned.m8n8.x2.shared.b16 {%0,%1}, [%2];"
                             : "=r"(bfh[nt][0]), "=r"(bfh[nt][1]) : "r"(bhBase + boff));
                asm volatile("ldmatrix.sync.aligned.m8n8.x2.shared.b16 {%0,%1}, [%2];"
                             : "=r"(bfl[nt][0]), "=r"(bfl[nt][1]) : "r"(blBase + boff));
            }
            #pragma unroll
            for (int mt = 0; mt < 4; mt++)
                #pragma unroll
                for (int nt = 0; nt < NT; nt++) {
                    MMA_F16(acc[mt][nt], af[mt], bfh[nt][0], bfh[nt][1]);
                    MMA_F16(acc[mt][nt], af[mt], bfl[nt][0], bfl[nt][1]);
                }
        }

        const int colBase = n0 + (lane & 3) * 2;
        const int rTop = rowBase + m0 + (lane >> 2);
        #pragma unroll
        for (int mt = 0; mt < 4; mt++) {
            int r0 = rTop + mt * 16, r1 = r0 + 8;
            #pragma unroll
            for (int nt = 0; nt < NT; nt++) {
                int c = colBase + nt * 8;
                __half2 v0 = __floats2half2_rn(fmaxf(acc[mt][nt][0], 0.f),
                                               fmaxf(acc[mt][nt][1], 0.f));
                __half2 v1 = __floats2half2_rn(fmaxf(acc[mt][nt][2], 0.f),
                                               fmaxf(acc[mt][nt][3], 0.f));
                if (r0 < M) *(__half2*)(C + (size_t)r0 * 128 + c) = v0;
                if (r1 < M) *(__half2*)(C + (size_t)r1 * 128 + c) = v1;
            }
        }
        __syncthreads();
    }
}

__global__ __launch_bounds__(256, 1)
void gemm_l2(const __half* __restrict__ A,
             const __half* __restrict__ Whi, const __half* __restrict__ Wlo,
             __half* __restrict__ lowhigh, __half* __restrict__ hm, int M) {
    constexpr int NB = 192, SA = 136, WN = 48, NT = 6, TILES = 2;
    extern __shared__ __align__(16) char smem[];
    __half* sA0 = (__half*)smem;
    __half* sA1 = sA0 + 128 * SA;
    __half* sBh = sA1 + 128 * SA;
    __half* sBl = sBh + NB * SA;

    const int tid = threadIdx.x, wid = tid >> 5, lane = tid & 31;

    #pragma unroll
    for (int i = tid; i < NB * 16; i += 256) {
        int r = i >> 4, c = i & 15;
        *(uint4*)(sBh + r * SA + c * 8) = *(const uint4*)(Whi + (size_t)r * 128 + c * 8);
        *(uint4*)(sBl + r * SA + c * 8) = *(const uint4*)(Wlo + (size_t)r * 128 + c * 8);
    }

    const uint32_t aAddr[2] = { smem_u32(sA0), smem_u32(sA1) };
    const int tileBase = blockIdx.x * TILES;

    prefetchA(aAddr[0], A, tileBase * 128, M, tid, SA);
    CP_COMMIT();

    const int m0 = (wid >> 2) * 64;
    const int n0 = (wid & 3) * WN;
    const int aj = lane >> 3;
    const int aRow = ((aj & 1) << 3) + (lane & 7);
    const int aK = (aj >> 1) << 3;
    const int bRow = lane & 7;
    const int bK = ((lane >> 3) & 1) << 3;
    const uint32_t bhBase = smem_u32(sBh);
    const uint32_t blBase = smem_u32(sBl);

    #pragma unroll
    for (int t = 0; t < TILES; t++) {
        const int rowBase = (tileBase + t) * 128;
        if (rowBase >= M) break;

        const int nextBase = rowBase + 128;
        if (t + 1 < TILES && nextBase < M)
            prefetchA(aAddr[(t + 1) & 1], A, nextBase, M, tid, SA);
        CP_COMMIT();
        CP_WAIT1();
        __syncthreads();

        const uint32_t aBase = aAddr[t & 1];

        float acc[4][NT][4];
        #pragma unroll
        for (int mt = 0; mt < 4; mt++)
            #pragma unroll
            for (int nt = 0; nt < NT; nt++)
                #pragma unroll
                for (int j = 0; j < 4; j++) acc[mt][nt][j] = 0.0f;

        #pragma unroll
        for (int ks = 0; ks < 8; ks++) {
            const int k0 = ks * 16;
            uint32_t af[4][4];
            #pragma unroll
            for (int mt = 0; mt < 4; mt++) {
                uint32_t addr = aBase + (uint32_t)(((m0 + mt * 16 + aRow) * SA + k0 + aK) * 2);
                asm volatile("ldmatrix.sync.aligned.m8n8.x4.shared.b16 {%0,%1,%2,%3}, [%4];"
                             : "=r"(af[mt][0]), "=r"(af[mt][1]), "=r"(af[mt][2]), "=r"(af[mt][3])
                             : "r"(addr));
            }
            uint32_t bfh[NT][2], bfl[NT][2];
            #pragma unroll
            for (int nt = 0; nt < NT; nt++) {
                uint32_t boff = (uint32_t)(((n0 + nt * 8 + bRow) * SA + k0 + bK) * 2);
                asm volatile("ldmatrix.sync.aligned.m8n8.x2.shared.b16 {%0,%1}, [%2];"
                             : "=r"(bfh[nt][0]), "=r"(bfh[nt][1]) : "r"(bhBase + boff));
                asm volatile("ldmatrix.sync.aligned.m8n8.x2.shared.b16 {%0,%1}, [%2];"
                             : "=r"(bfl[nt][0]), "=r"(bfl[nt][1]) : "r"(blBase + boff));
            }
            #pragma unroll
            for (int mt = 0; mt < 4; mt++)
                #pragma unroll
                for (int nt = 0; nt < NT; nt++) {
                    MMA_F16(acc[mt][nt], af[mt], bfh[nt][0], bfh[nt][1]);
                    MMA_F16(acc[mt][nt], af[mt], bfl[nt][0], bfl[nt][1]);
                }
        }

        const int colBase = n0 + (lane & 3) * 2;
        const int rTop = rowBase + m0 + (lane >> 2);
        #pragma unroll
        for (int mt = 0; mt < 4; mt++) {
            int r0 = rTop + mt * 16, r1 = r0 + 8;
            #pragma unroll
            for (int nt = 0; nt < NT; nt++) {
                int c = colBase + nt * 8;
                float p0x = acc[mt][nt][0], p0y = acc[mt][nt][1];
                float p1x = acc[mt][nt][2], p1y = acc[mt][nt][3];
                if (c < 128) {
                    if (r0 < M) { __half2 v = __floats2half2_rn(p0x, p0y);
                                  *(__half2*)(lowhigh + (size_t)r0 * 128 + c) = v; }
                    if (r1 < M) { __half2 v = __floats2half2_rn(p1x, p1y);
                                  *(__half2*)(lowhigh + (size_t)r1 * 128 + c) = v; }
                } else {
                    p0x = fmaxf(p0x, 0.f); p0y = fmaxf(p0y, 0.f);
                    p1x = fmaxf(p1x, 0.f); p1y = fmaxf(p1y, 0.f);
                    int ch = c - 128;
                    if (r0 < M) { __half2 v = __floats2half2_rn(p0x, p0y);
                                  *(__half2*)(hm + (size_t)r0 * 64 + ch) = v; }
                    if (r1 < M) { __half2 v = __floats2half2_rn(p1x, p1y);
                                  *(__half2*)(hm + (size_t)r1 * 64 + ch) = v; }
                }
            }
        }
        __syncthreads();
    }
}

// ------ layer-1 attention combine + relu -> fea16 --------------------------

__global__ __launch_bounds__(256)
void att_fuse(const __half* __restrict__ ol, const __half* __restrict__ oh,
              const __half* __restrict__ om,
              const float* __restrict__ vl, const float* __restrict__ vh,
              const float* __restrict__ vm, const float* __restrict__ av,
              __half* __restrict__ fea16, int n) {
    int gw = (blockIdx.x * blockDim.x + threadIdx.x) >> 5;
    if (gw >= n) return;
    const int lane = threadIdx.x & 31;
    const size_t base = (size_t)gw * 128 + lane * 4;

    uint2 lv = *(const uint2*)(ol + base);
    uint2 hv = *(const uint2*)(oh + base);
    uint2 mv = *(const uint2*)(om + base);
    float2 l01 = __half22float2(*(__half2*)&lv.x), l23 = __half22float2(*(__half2*)&lv.y);
    float2 h01 = __half22float2(*(__half2*)&hv.x), h23 = __half22float2(*(__half2*)&hv.y);
    float2 m01 = __half22float2(*(__half2*)&mv.x), m23 = __half22float2(*(__half2*)&mv.y);
    float low[4] = {l01.x, l01.y, l23.x, l23.y};
    float high[4] = {h01.x, h01.y, h23.x, h23.y};
    float mlp[4] = {m01.x, m01.y, m23.x, m23.y};

    float dl = 0.f, dh = 0.f, dm = 0.f;
    #pragma unroll
    for (int i = 0; i < 4; i++) {
        dl += low[i]  * vl[lane * 4 + i];
        dh += high[i] * vh[lane * 4 + i];
        dm += mlp[i]  * vm[lane * 4 + i];
    }
    #pragma unroll
    for (int o = 16; o > 0; o >>= 1) {
        dl += __shfl_xor_sync(0xffffffffu, dl, o);
        dh += __shfl_xor_sync(0xffffffffu, dh, o);
        dm += __shfl_xor_sync(0xffffffffu, dm, o);
    }

    float sl = 1.0f / (1.0f + __expf(-dl));
    float sh = 1.0f / (1.0f + __expf(-dh));
    float sm = 1.0f / (1.0f + __expf(-dm));

    float t0 = (sl * av[0] + sh * av[3] + sm * av[6]) * (1.0f / 3.0f);
    float t1 = (sl * av[1] + sh * av[4] + sm * av[7]) * (1.0f / 3.0f);
    float t2 = (sl * av[2] + sh * av[5] + sm * av[8]) * (1.0f / 3.0f);
    float mx = fmaxf(t0, fmaxf(t1, t2));
    float w0 = __expf(t0 - mx), w1 = __expf(t1 - mx), w2 = __expf(t2 - mx);
    float wsum = w0 + w1 + w2;
    float a0 = 3.0f * w0 / wsum, a1 = 3.0f * w1 / wsum, a2 = 3.0f * w2 / wsum;

    float tmp[4];
    #pragma unroll
    for (int i = 0; i < 4; i++)
        tmp[i] = fmaxf(a0 * low[i] + a1 * high[i] + a2 * mlp[i], 0.f);

    __half2 p0 = __floats2half2_rn(tmp[0], tmp[1]);
    __half2 p1 = __floats2half2_rn(tmp[2], tmp[3]);
    uint2 o;
    o.x = *(uint32_t*)&p0; o.y = *(uint32_t*)&p1;
    ((uint2*)fea16)[base / 4] = o;
}

// ---- layer-2 fused spmm + attention (fp16 gather, unroll8) ----------------

__global__ __launch_bounds__(256)
void acm_fuse64(const __half* __restrict__ hlh16, const __half* __restrict__ hm16,
                const int* __restrict__ rowptr, const int* __restrict__ col,
                const float* __restrict__ vl, const float* __restrict__ vh,
                const float* __restrict__ vm, const float* __restrict__ av,
                float* __restrict__ out, int n) {
    int gw = (blockIdx.x * blockDim.x + threadIdx.x) >> 5;
    if (gw >= n) return;
    const int lane = threadIdx.x & 31;
    const int s = rowptr[gw], e = rowptr[gw + 1];
    const bool hiHalf = lane >= 16;

    float acc[4] = {0.f, 0.f, 0.f, 0.f};

    for (int base = s; base < e; base += 32) {
        int idx = base + lane;
        int c = (idx < e) ? col[idx] : 0;
        int cnt = min(32, e - base);
        int k = 0;
        for (; k + 8 <= cnt; k += 8) {
            uint2 v[8];
            #pragma unroll
            for (int j = 0; j < 8; j++) {
                int cc = __shfl_sync(0xffffffffu, c, k + j);
                v[j] = __ldg((const uint2*)(hlh16 + (size_t)cc * 128 + lane * 4));
            }
            #pragma unroll
            for (int j = 0; j < 8; j++) {
                float2 a = __half22float2(*(__half2*)&v[j].x);
                float2 b = __half22float2(*(__half2*)&v[j].y);
                acc[0] += a.x; acc[1] += a.y; acc[2] += b.x; acc[3] += b.y;
            }
        }
        for (; k < cnt; k++) {
            int cc = __shfl_sync(0xffffffffu, c, k);
            uint2 v = __ldg((const uint2*)(hlh16 + (size_t)cc * 128 + lane * 4));
            float2 a = __half22float2(*(__half2*)&v.x);
            float2 b = __half22float2(*(__half2*)&v.y);
            acc[0] += a.x; acc[1] += a.y; acc[2] += b.x; acc[3] += b.y;
        }
    }

    const float inv = (e > s) ? 1.0f / (float)(e - s) : 0.0f;

    uint2 ov = *(const uint2*)(hlh16 + (size_t)gw * 128 + lane * 4);
    float2 o01 = __half22float2(*(__half2*)&ov.x);
    float2 o23 = __half22float2(*(__half2*)&ov.y);
    float own[4] = {o01.x, o01.y, o23.x, o23.y};

    uint2 mv = *(const uint2*)(hm16 + (size_t)gw * 64 + (lane & 15) * 4);
    float2 m01 = __half22float2(*(__half2*)&mv.x);
    float2 m23 = __half22float2(*(__half2*)&mv.y);
    float mlp[4] = {m01.x, m01.y, m23.x, m23.y};

    float val[4];
    #pragma unroll
    for (int j = 0; j < 4; j++) {
        float a = inv * acc[j];
        val[j] = hiHalf ? fmaxf(own[j] - a, 0.f) : fmaxf(a, 0.f);
    }

    float dl = 0.f, dh = 0.f, dm = 0.f;
    if (!hiHalf) {
        #pragma unroll
        for (int j = 0; j < 4; j++) {
            dl += val[j] * vl[lane * 4 + j];
            dm += mlp[j] * vm[lane * 4 + j];
        }
    } else {
        #pragma unroll
        for (int j = 0; j < 4; j++)
            dh += val[j] * vh[(lane - 16) * 4 + j];
    }
    #pragma unroll
    for (int o = 16; o > 0; o >>= 1) {
        dl += __shfl_xor_sync(0xffffffffu, dl, o);
        dh += __shfl_xor_sync(0xffffffffu, dh, o);
        dm += __shfl_xor_sync(0xffffffffu, dm, o);
    }

    float sl = 1.0f / (1.0f + __expf(-dl));
    float sh = 1.0f / (1.0f + __expf(-dh));
    float sm = 1.0f / (1.0f + __expf(-dm));

    float t0 = (sl * av[0] + sh * av[3] + sm * av[6]) * (1.0f / 3.0f);
    float t1 = (sl * av[1] + sh * av[4] + sm * av[7]) * (1.0f / 3.0f);
    float t2 = (sl * av[2] + sh * av[5] + sm * av[8]) * (1.0f / 3.0f);
    float mx = fmaxf(t0, fmaxf(t1, t2));
    float w0 = __expf(t0 - mx), w1 = __expf(t1 - mx), w2 = __expf(t2 - mx);
    float wsum = w0 + w1 + w2;
    float a0 = 3.0f * w0 / wsum, a1 = 3.0f * w1 / wsum, a2 = 3.0f * w2 / wsum;

    float part[4], other[4];
    #pragma unroll
    for (int j = 0; j < 4; j++)
        part[j] = hiHalf ? a1 * val[j] : a0 * val[j];
    #pragma unroll
    for (int j = 0; j < 4; j++)
        other[j] = __shfl_xor_sync(0xffffffffu, part[j], 16);

    if (!hiHalf) {
        float4 o4;
        o4.x = part[0] + other[0] + a2 * mlp[0];
        o4.y = part[1] + other[1] + a2 * mlp[1];
        o4.z = part[2] + other[2] + a2 * mlp[2];
        o4.w = part[3] + other[3] + a2 * mlp[3];
        *(float4*)(out + (size_t)gw * 64 + lane * 4) = o4;
    }
}

// ------------------------------ launch -------------------------------------

extern "C" void kernel_launch(void* const* d_in, const int* in_sizes, int n_in,
                              void* d_out, int out_size) {
    const float* x    = (const float*)d_in[0];
    const int*   ei   = (const int*)d_in[1];
    const float* Wl1  = (const float*)d_in[2];
    const float* Wh1  = (const float*)d_in[3];
    const float* Wm1  = (const float*)d_in[4];
    const float* vl1  = (const float*)d_in[5];
    const float* vh1  = (const float*)d_in[6];
    const float* vm1  = (const float*)d_in[7];
    const float* av1  = (const float*)d_in[8];
    const float* Wl2  = (const float*)d_in[9];
    const float* Wh2  = (const float*)d_in[10];
    const float* Wm2  = (const float*)d_in[11];
    const float* vl2  = (const float*)d_in[12];
    const float* vh2  = (const float*)d_in[13];
    const float* vm2  = (const float*)d_in[14];
    const float* av2  = (const float*)d_in[15];

    const int n = in_sizes[0] / 128;
    const int E = in_sizes[1] / 2;
    const int* row = ei;
    const int* colsrc = ei + E;

    int *deg, *rowptr, *col, *ticket;
    __half *x16, *agg16, *dif16, *hl16, *hh16, *hmm16, *fea16, *lh16, *hm16;
    __half *w1hi, *w1lo, *w2hi, *w2lo;
    cudaGetSymbolAddress((void**)&deg, g_deg);
    cudaGetSymbolAddress((void**)&rowptr, g_rowptr);
    cudaGetSymbolAddress((void**)&col, g_col);
    cudaGetSymbolAddress((void**)&ticket, g_ticket);
    cudaGetSymbolAddress((void**)&x16, g_x16);
    cudaGetSymbolAddress((void**)&agg16, g_agg16);
    cudaGetSymbolAddress((void**)&dif16, g_dif16);
    cudaGetSymbolAddress((void**)&hl16, g_hl16);
    cudaGetSymbolAddress((void**)&hh16, g_hh16);
    cudaGetSymbolAddress((void**)&hmm16, g_hmm16);
    cudaGetSymbolAddress((void**)&fea16, g_fea16);
    cudaGetSymbolAddress((void**)&lh16, g_lh16);
    cudaGetSymbolAddress((void**)&hm16, g_hm16);
    cudaGetSymbolAddress((void**)&w1hi, g_w1hi);
    cudaGetSymbolAddress((void**)&w1lo, g_w1lo);
    cudaGetSymbolAddress((void**)&w2hi, g_w2hi);
    cudaGetSymbolAddress((void**)&w2lo, g_w2lo);

    float* out = (float*)d_out;

    const int SA = 136;
    const int smem1 = (2 * 128 * SA + 2 * 128 * SA) * 2;
    const int smem2 = (2 * 128 * SA + 2 * 192 * SA) * 2;
    cudaFuncSetAttribute(gemm_l1, cudaFuncAttributeMaxDynamicSharedMemorySize, smem1);
    cudaFuncSetAttribute(gemm_l2, cudaFuncAttributeMaxDynamicSharedMemorySize, smem2);

    // prologue: zero deg, then fused deg-atomics(+ticket) + x16 + W converts
    zero_kernel<<<(n + 255) / 256, 256>>>(deg, n);
    {
        int tot = E + n * 32 + 3 * 128 * 128 + 3 * 64 * 128;
        work_kernel<<<(tot + 255) / 256, 256>>>(row, deg, ticket, E, x, x16,
                                                Wl1, Wh1, Wm1, w1hi, w1lo,
                                                Wl2, Wh2, Wm2, w2hi, w2lo, n);
    }
    scan_kernel<<<1, 1024>>>(deg, rowptr, n);
    scatter_kernel<<<(E + 255) / 256, 256>>>(row, colsrc, rowptr, ticket, col, E);

    const int gx4 = (n + 511) / 512;   // gemm_l1: 4 tiles/CTA
    const int gx2 = (n + 255) / 256;   // gemm_l2: 2 tiles/CTA

    spmm_cvt<<<(n + 7) / 8, 256>>>(x16, rowptr, col, agg16, dif16, n);
    {
        dim3 grid(gx4, 3);
        gemm_l1<<<grid, 256, smem1>>>(agg16, dif16, x16, w1hi, w1lo, hl16, hh16, hmm16, n);
    }
    att_fuse<<<(n + 7) / 8, 256>>>(hl16, hh16, hmm16, vl1, vh1, vm1, av1, fea16, n);

    gemm_l2<<<gx2, 256, smem2>>>(fea16, w2hi, w2lo, lh16, hm16, n);
    acm_fuse64<<<(n + 7) / 8, 256>>>(lh16, hm16, rowptr, col,
                                     vl2, vh2, vm2, av2, out, n);
}

// round 17
// speedup vs baseline: 1.1752x; 1.1752x over previous
#include <cuda_runtime.h>
#include <cuda_bf16.h>
#include <cuda_fp16.h>
#include <cstdint>
#include <math.h>

// ---------------------------------------------------------------------------
// ACM-GCN on GB300, round 17 = round 16 + u16 tickets + parallel 3-phase scan
// (98-block local scan -> 1-block scan of block sums -> offset add), replacing
// the serial single-block scan that idled 147 SMs.
// ---------------------------------------------------------------------------

#define MAXN 100000
#define MAXE 1600000
#define NBLK 128

__device__ int   g_deg[MAXN];
__device__ int   g_rowptr[MAXN + 1];
__device__ int   g_bsum[NBLK];
__device__ int   g_boff[NBLK];
__device__ int   g_col[MAXE];
__device__ unsigned short g_ticket[MAXE];
__device__ __half g_x16[(size_t)MAXN * 128];
__device__ __half g_agg16[(size_t)MAXN * 128];
__device__ __half g_dif16[(size_t)MAXN * 128];
__device__ __half g_hl16[(size_t)MAXN * 128];
__device__ __half g_hh16[(size_t)MAXN * 128];
__device__ __half g_hmm16[(size_t)MAXN * 128];
__device__ __half g_fea16[(size_t)MAXN * 128];
__device__ __half g_lh16[(size_t)MAXN * 128];
__device__ __half g_hm16[(size_t)MAXN * 64];
__device__ __half g_w1hi[3 * 128 * 128];
__device__ __half g_w1lo[3 * 128 * 128];
__device__ __half g_w2hi[3 * 64 * 128];
__device__ __half g_w2lo[3 * 64 * 128];

__device__ __forceinline__ uint32_t smem_u32(const void* p) {
    uint32_t a;
    asm("{ .reg .u64 t; cvta.to.shared.u64 t, %1; cvt.u32.u64 %0, t; }"
        : "=r"(a) : "l"(p));
    return a;
}

#define CP_ASYNC16(dst, src, sz) \
    asm volatile("cp.async.cg.shared.global [%0], [%1], 16, %2;" \
                 :: "r"(dst), "l"(src), "r"(sz))
#define CP_COMMIT() asm volatile("cp.async.commit_group;" ::: "memory")
#define CP_WAIT1()  asm volatile("cp.async.wait_group 1;" ::: "memory")

// --------------------------- CSR construction -----------------------------

__global__ void zero_kernel(int* deg, int n) {
    int i = blockIdx.x * blockDim.x + threadIdx.x;
    if (i < n) deg[i] = 0;
}

// fused: deg atomics (+u16 ticket) + x16 convert + W1/W2 split converts
__global__ void work_kernel(const int* __restrict__ row, int* deg,
                            unsigned short* __restrict__ ticket, int E,
                            const float* __restrict__ x, __half* __restrict__ x16,
                            const float* __restrict__ W0a, const float* __restrict__ W1a,
                            const float* __restrict__ W2a,
                            __half* __restrict__ w1hi, __half* __restrict__ w1lo,
                            const float* __restrict__ W0b, const float* __restrict__ W1b,
                            const float* __restrict__ W2b,
                            __half* __restrict__ w2hi, __half* __restrict__ w2lo,
                            int n) {
    const int xcnt = n * 32;
    const int w1cnt = 3 * 128 * 128;
    const int w2cnt = 3 * 64 * 128;
    int id = blockIdx.x * blockDim.x + threadIdx.x;

    if (id < E) {
        ticket[id] = (unsigned short)atomicAdd(&deg[row[id]], 1);
        return;
    }
    id -= E;
    if (id < xcnt) {
        float4 v = ((const float4*)x)[id];
        __half2 p0 = __floats2half2_rn(v.x, v.y);
        __half2 p1 = __floats2half2_rn(v.z, v.w);
        uint2 o;
        o.x = *(uint32_t*)&p0; o.y = *(uint32_t*)&p1;
        ((uint2*)x16)[id] = o;
        return;
    }
    id -= xcnt;
    if (id < w1cnt) {
        const int K = 128, Nn = 128;
        int y = id / (K * Nn);
        int rem = id - y * K * Nn;
        int k = rem / Nn;
        int nn = rem - k * Nn;
        const float* W = (y == 0) ? W0a : (y == 1) ? W1a : W2a;
        float w = W[k * Nn + nn];
        __half h = __float2half_rn(w);
        __half l = __float2half_rn(w - __half2float(h));
        w1hi[(size_t)y * Nn * K + nn * K + k] = h;
        w1lo[(size_t)y * Nn * K + nn * K + k] = l;
        return;
    }
    id -= w1cnt;
    if (id < w2cnt) {
        const int K = 128, Nn = 64;
        int y = id / (K * Nn);
        int rem = id - y * K * Nn;
        int k = rem / Nn;
        int nn = rem - k * Nn;
        const float* W = (y == 0) ? W0b : (y == 1) ? W1b : W2b;
        float w = W[k * Nn + nn];
        __half h = __float2half_rn(w);
        __half l = __float2half_rn(w - __half2float(h));
        w2hi[(size_t)y * Nn * K + nn * K + k] = h;
        w2lo[(size_t)y * Nn * K + nn * K + k] = l;
    }
}

// phase A: per-block (1024 elems) exclusive scan + block sums
__global__ void scanA_kernel(const int* __restrict__ deg, int* __restrict__ rowptr,
                             int* __restrict__ bsum, int n) {
    __shared__ int wsum[32];
    const int tid = threadIdx.x, lane = tid & 31, w = tid >> 5;
    const int i = blockIdx.x * 1024 + tid;
    int v = (i < n) ? deg[i] : 0;
    int x = v;
    #pragma unroll
    for (int o = 1; o < 32; o <<= 1) {
        int y = __shfl_up_sync(0xffffffffu, x, o);
        if (lane >= o) x += y;
    }
    if (lane == 31) wsum[w] = x;
    __syncthreads();
    if (w == 0) {
        int t = wsum[lane];
        #pragma unroll
        for (int o = 1; o < 32; o <<= 1) {
            int y = __shfl_up_sync(0xffffffffu, t, o);
            if (lane >= o) t += y;
        }
        wsum[lane] = t;
    }
    __syncthreads();
    int excl = (w > 0 ? wsum[w - 1] : 0) + x - v;
    if (i < n) rowptr[i] = excl;
    if (tid == 1023) bsum[blockIdx.x] = excl + v;
}

// phase B: scan the block sums (single small block), write rowptr[n]
__global__ void scanB_kernel(const int* __restrict__ bsum, int* __restrict__ boff,
                             int* __restrict__ rowptr, int nblk, int n) {
    __shared__ int s[NBLK];
    const int tid = threadIdx.x;
    int v = (tid < nblk) ? bsum[tid] : 0;
    s[tid] = v;
    __syncthreads();
    // simple Hillis-Steele inclusive scan over NBLK=128
    for (int o = 1; o < NBLK; o <<= 1) {
        int t = (tid >= o) ? s[tid - o] : 0;
        __syncthreads();
        s[tid] += t;
        __syncthreads();
    }
    if (tid < nblk) boff[tid] = s[tid] - v;       // exclusive
    if (tid == nblk - 1) rowptr[n] = s[tid];
}

// phase C: add block offsets
__global__ void scanC_kernel(int* __restrict__ rowptr, const int* __restrict__ boff, int n) {
    int i = blockIdx.x * blockDim.x + threadIdx.x;
    if (i < n) rowptr[i] += boff[i >> 10];
}

// atomic-free scatter via ticket
__global__ void scatter_kernel(const int* __restrict__ row, const int* __restrict__ colsrc,
                               const int* __restrict__ rowptr,
                               const unsigned short* __restrict__ ticket,
                               int* __restrict__ colout, int E) {
    int e = blockIdx.x * blockDim.x + threadIdx.x;
    if (e < E) {
        int r = row[e];
        colout[rowptr[r] + (int)ticket[e]] = colsrc[e];
    }
}

// -------------------- layer-1 spmm (fp16 gather, unroll8) ------------------

__global__ __launch_bounds__(256)
void spmm_cvt(const __half* __restrict__ x16,
              const int* __restrict__ rowptr, const int* __restrict__ col,
              __half* __restrict__ agg16, __half* __restrict__ dif16, int n) {
    int gw = (blockIdx.x * blockDim.x + threadIdx.x) >> 5;
    if (gw >= n) return;
    const int lane = threadIdx.x & 31;
    const int s = rowptr[gw], e = rowptr[gw + 1];

    float acc[4] = {0.f, 0.f, 0.f, 0.f};

    for (int base = s; base < e; base += 32) {
        int idx = base + lane;
        int c = (idx < e) ? col[idx] : 0;
        int cnt = min(32, e - base);
        int k = 0;
        for (; k + 8 <= cnt; k += 8) {
            uint2 v[8];
            #pragma unroll
            for (int j = 0; j < 8; j++) {
                int cc = __shfl_sync(0xffffffffu, c, k + j);
                v[j] = __ldg((const uint2*)(x16 + (size_t)cc * 128 + lane * 4));
            }
            #pragma unroll
            for (int j = 0; j < 8; j++) {
                float2 a = __half22float2(*(__half2*)&v[j].x);
                float2 b = __half22float2(*(__half2*)&v[j].y);
                acc[0] += a.x; acc[1] += a.y; acc[2] += b.x; acc[3] += b.y;
            }
        }
        for (; k < cnt; k++) {
            int cc = __shfl_sync(0xffffffffu, c, k);
            uint2 v = __ldg((const uint2*)(x16 + (size_t)cc * 128 + lane * 4));
            float2 a = __half22float2(*(__half2*)&v.x);
            float2 b = __half22float2(*(__half2*)&v.y);
            acc[0] += a.x; acc[1] += a.y; acc[2] += b.x; acc[3] += b.y;
        }
    }

    const float inv = (e > s) ? 1.0f / (float)(e - s) : 0.0f;
    uint2 ov = *(const uint2*)(x16 + (size_t)gw * 128 + lane * 4);
    float2 o01 = __half22float2(*(__half2*)&ov.x);
    float2 o23 = __half22float2(*(__half2*)&ov.y);
    float own[4] = {o01.x, o01.y, o23.x, o23.y};

    float agg[4], dif[4];
    #pragma unroll
    for (int i = 0; i < 4; i++) {
        agg[i] = inv * acc[i];
        dif[i] = own[i] - agg[i];
    }

    const size_t off = ((size_t)gw * 128 + lane * 4) / 4;
    __half2 a0 = __floats2half2_rn(agg[0], agg[1]);
    __half2 a1 = __floats2half2_rn(agg[2], agg[3]);
    __half2 d0 = __floats2half2_rn(dif[0], dif[1]);
    __half2 d1 = __floats2half2_rn(dif[2], dif[3]);
    uint2 av, dv;
    av.x = *(uint32_t*)&a0; av.y = *(uint32_t*)&a1;
    dv.x = *(uint32_t*)&d0; dv.y = *(uint32_t*)&d1;
    ((uint2*)agg16)[off] = av;
    ((uint2*)dif16)[off] = dv;
}

// ----------------------- fp16 2-product mma GEMMs --------------------------

#define MMA_F16(acc, af, b0, b1)                                              \
    asm volatile("mma.sync.aligned.m16n8k16.row.col.f32.f16.f16.f32 "         \
                 "{%0,%1,%2,%3}, {%4,%5,%6,%7}, {%8,%9}, {%0,%1,%2,%3};"      \
                 : "+f"((acc)[0]), "+f"((acc)[1]), "+f"((acc)[2]), "+f"((acc)[3]) \
                 : "r"((af)[0]), "r"((af)[1]), "r"((af)[2]), "r"((af)[3]),    \
                   "r"(b0), "r"(b1))

__device__ __forceinline__ void prefetchA(uint32_t bufAddr, const __half* A,
                                          int rowBase, int M, int tid, int SA) {
    #pragma unroll
    for (int i = tid; i < 128 * 16; i += 256) {
        int r = i >> 4, c = i & 15;
        int gr = rowBase + r;
        uint32_t dst = bufAddr + (uint32_t)((r * SA + c * 8) * 2);
        const __half* src = A + (size_t)gr * 128 + c * 8;
        int sz = (gr < M) ? 16 : 0;
        CP_ASYNC16(dst, src, sz);
    }
}

__global__ __launch_bounds__(256, 1)
void gemm_l1(const __half* __restrict__ A0, const __half* __restrict__ A1,
             const __half* __restrict__ A2,
             const __half* __restrict__ Whi, const __half* __restrict__ Wlo,
             __half* __restrict__ C0, __half* __restrict__ C1, __half* __restrict__ C2,
             int M) {
    constexpr int NB = 128, SA = 136, WN = 32, NT = 4, TILES = 4;
    extern __shared__ __align__(16) char smem[];
    __half* sA0 = (__half*)smem;
    __half* sA1 = sA0 + 128 * SA;
    __half* sBh = sA1 + 128 * SA;
    __half* sBl = sBh + NB * SA;

    const int tid = threadIdx.x, wid = tid >> 5, lane = tid & 31;
    const int y = blockIdx.y;
    const __half* A = (y == 0) ? A0 : (y == 1) ? A1 : A2;
    const __half* bh = Whi + (size_t)y * NB * 128;
    const __half* bl = Wlo + (size_t)y * NB * 128;
    __half* C = (y == 0) ? C0 : (y == 1) ? C1 : C2;

    #pragma unroll
    for (int i = tid; i < NB * 16; i += 256) {
        int r = i >> 4, c = i & 15;
        *(uint4*)(sBh + r * SA + c * 8) = *(const uint4*)(bh + r * 128 + c * 8);
        *(uint4*)(sBl + r * SA + c * 8) = *(const uint4*)(bl + r * 128 + c * 8);
    }

    const uint32_t aAddr[2] = { smem_u32(sA0), smem_u32(sA1) };
    const int tileBase = blockIdx.x * TILES;

    prefetchA(aAddr[0], A, tileBase * 128, M, tid, SA);
    CP_COMMIT();

    const int m0 = (wid >> 2) * 64;
    const int n0 = (wid & 3) * WN;
    const int aj = lane >> 3;
    const int aRow = ((aj & 1) << 3) + (lane & 7);
    const int aK = (aj >> 1) << 3;
    const int bRow = lane & 7;
    const int bK = ((lane >> 3) & 1) << 3;
    const uint32_t bhBase = smem_u32(sBh);
    const uint32_t blBase = smem_u32(sBl);

    #pragma unroll
    for (int t = 0; t < TILES; t++) {
        const int rowBase = (tileBase + t) * 128;
        if (rowBase >= M) break;

        const int nextBase = rowBase + 128;
        if (t + 1 < TILES && nextBase < M)
            prefetchA(aAddr[(t + 1) & 1], A, nextBase, M, tid, SA);
        CP_COMMIT();
        CP_WAIT1();
        __syncthreads();

        const uint32_t aBase = aAddr[t & 1];

        float acc[4][NT][4];
        #pragma unroll
        for (int mt = 0; mt < 4; mt++)
            #pragma unroll
            for (int nt = 0; nt < NT; nt++)
                #pragma unroll
                for (int j = 0; j < 4; j++) acc[mt][nt][j] = 0.0f;

        #pragma unroll
        for (int ks = 0; ks < 8; ks++) {
            const int k0 = ks * 16;
            uint32_t af[4][4];
            #pragma unroll
            for (int mt = 0; mt < 4; mt++) {
                uint32_t addr = aBase + (uint32_t)(((m0 + mt * 16 + aRow) * SA + k0 + aK) * 2);
                asm volatile("ldmatrix.sync.aligned.m8n8.x4.shared.b16 {%0,%1,%2,%3}, [%4];"
                             : "=r"(af[mt][0]), "=r"(af[mt][1]), "=r"(af[mt][2]), "=r"(af[mt][3])
                             : "r"(addr));
            }
            uint32_t bfh[NT][2], bfl[NT][2];
            #pragma unroll
            for (int nt = 0; nt < NT; nt++) {
                uint32_t boff = (uint32_t)(((n0 + nt * 8 + bRow) * SA + k0 + bK) * 2);
                asm volatile("ldmatrix.sync.aligned.m8n8.x2.shared.b16 {%0,%1}, [%2];"
                             : "=r"(bfh[nt][0]), "=r"(bfh[nt][1]) : "r"(bhBase + boff));
                asm volatile("ldmatrix.sync.aligned.m8n8.x2.shared.b16 {%0,%1}, [%2];"
                             : "=r"(bfl[nt][0]), "=r"(bfl[nt][1]) : "r"(blBase + boff));
            }
            #pragma unroll
            for (int mt = 0; mt < 4; mt++)
                #pragma unroll
                for (int nt = 0; nt < NT; nt++) {
                    MMA_F16(acc[mt][nt], af[mt], bfh[nt][0], bfh[nt][1]);
                    MMA_F16(acc[mt][nt], af[mt], bfl[nt][0], bfl[nt][1]);
                }
        }

        const int colBase = n0 + (lane & 3) * 2;
        const int rTop = rowBase + m0 + (lane >> 2);
        #pragma unroll
        for (int mt = 0; mt < 4; mt++) {
            int r0 = rTop + mt * 16, r1 = r0 + 8;
            #pragma unroll
            for (int nt = 0; nt < NT; nt++) {
                int c = colBase + nt * 8;
                __half2 v0 = __floats2half2_rn(fmaxf(acc[mt][nt][0], 0.f),
                                               fmaxf(acc[mt][nt][1], 0.f));
                __half2 v1 = __floats2half2_rn(fmaxf(acc[mt][nt][2], 0.f),
                                               fmaxf(acc[mt][nt][3], 0.f));
                if (r0 < M) *(__half2*)(C + (size_t)r0 * 128 + c) = v0;
                if (r1 < M) *(__half2*)(C + (size_t)r1 * 128 + c) = v1;
            }
        }
        __syncthreads();
    }
}

__global__ __launch_bounds__(256, 1)
void gemm_l2(const __half* __restrict__ A,
             const __half* __restrict__ Whi, const __half* __restrict__ Wlo,
             __half* __restrict__ lowhigh, __half* __restrict__ hm, int M) {
    constexpr int NB = 192, SA = 136, WN = 48, NT = 6, TILES = 2;
    extern __shared__ __align__(16) char smem[];
    __half* sA0 = (__half*)smem;
    __half* sA1 = sA0 + 128 * SA;
    __half* sBh = sA1 + 128 * SA;
    __half* sBl = sBh + NB * SA;

    const int tid = threadIdx.x, wid = tid >> 5, lane = tid & 31;

    #pragma unroll
    for (int i = tid; i < NB * 16; i += 256) {
        int r = i >> 4, c = i & 15;
        *(uint4*)(sBh + r * SA + c * 8) = *(const uint4*)(Whi + (size_t)r * 128 + c * 8);
        *(uint4*)(sBl + r * SA + c * 8) = *(const uint4*)(Wlo + (size_t)r * 128 + c * 8);
    }

    const uint32_t aAddr[2] = { smem_u32(sA0), smem_u32(sA1) };
    const int tileBase = blockIdx.x * TILES;

    prefetchA(aAddr[0], A, tileBase * 128, M, tid, SA);
    CP_COMMIT();

    const int m0 = (wid >> 2) * 64;
    const int n0 = (wid & 3) * WN;
    const int aj = lane >> 3;
    const int aRow = ((aj & 1) << 3) + (lane & 7);
    const int aK = (aj >> 1) << 3;
    const int bRow = lane & 7;
    const int bK = ((lane >> 3) & 1) << 3;
    const uint32_t bhBase = smem_u32(sBh);
    const uint32_t blBase = smem_u32(sBl);

    #pragma unroll
    for (int t = 0; t < TILES; t++) {
        const int rowBase = (tileBase + t) * 128;
        if (rowBase >= M) break;

        const int nextBase = rowBase + 128;
        if (t + 1 < TILES && nextBase < M)
            prefetchA(aAddr[(t + 1) & 1], A, nextBase, M, tid, SA);
        CP_COMMIT();
        CP_WAIT1();
        __syncthreads();

        const uint32_t aBase = aAddr[t & 1];

        float acc[4][NT][4];
        #pragma unroll
        for (int mt = 0; mt < 4; mt++)
            #pragma unroll
            for (int nt = 0; nt < NT; nt++)
                #pragma unroll
                for (int j = 0; j < 4; j++) acc[mt][nt][j] = 0.0f;

        #pragma unroll
        for (int ks = 0; ks < 8; ks++) {
            const int k0 = ks * 16;
            uint32_t af[4][4];
            #pragma unroll
            for (int mt = 0; mt < 4; mt++) {
                uint32_t addr = aBase + (uint32_t)(((m0 + mt * 16 + aRow) * SA + k0 + aK) * 2);
                asm volatile("ldmatrix.sync.aligned.m8n8.x4.shared.b16 {%0,%1,%2,%3}, [%4];"
                             : "=r"(af[mt][0]), "=r"(af[mt][1]), "=r"(af[mt][2]), "=r"(af[mt][3])
                             : "r"(addr));
            }
            uint32_t bfh[NT][2], bfl[NT][2];
            #pragma unroll
            for (int nt = 0; nt < NT; nt++) {
                uint32_t boff = (uint32_t)(((n0 + nt * 8 + bRow) * SA + k0 + bK) * 2);
                asm volatile("ldmatrix.sync.aligned.m8n8.x2.shared.b16 {%0,%1}, [%2];"
                             : "=r"(bfh[nt][0]), "=r"(bfh[nt][1]) : "r"(bhBase + boff));
                asm volatile("ldmatrix.sync.aligned.m8n8.x2.shared.b16 {%0,%1}, [%2];"
                             : "=r"(bfl[nt][0]), "=r"(bfl[nt][1]) : "r"(blBase + boff));
            }
            #pragma unroll
            for (int mt = 0; mt < 4; mt++)
                #pragma unroll
                for (int nt = 0; nt < NT; nt++) {
                    MMA_F16(acc[mt][nt], af[mt], bfh[nt][0], bfh[nt][1]);
                    MMA_F16(acc[mt][nt], af[mt], bfl[nt][0], bfl[nt][1]);
                }
        }

        const int colBase = n0 + (lane & 3) * 2;
        const int rTop = rowBase + m0 + (lane >> 2);
        #pragma unroll
        for (int mt = 0; mt < 4; mt++) {
            int r0 = rTop + mt * 16, r1 = r0 + 8;
            #pragma unroll
            for (int nt = 0; nt < NT; nt++) {
                int c = colBase + nt * 8;
                float p0x = acc[mt][nt][0], p0y = acc[mt][nt][1];
                float p1x = acc[mt][nt][2], p1y = acc[mt][nt][3];
                if (c < 128) {
                    if (r0 < M) { __half2 v = __floats2half2_rn(p0x, p0y);
                                  *(__half2*)(lowhigh + (size_t)r0 * 128 + c) = v; }
                    if (r1 < M) { __half2 v = __floats2half2_rn(p1x, p1y);
                                  *(__half2*)(lowhigh + (size_t)r1 * 128 + c) = v; }
                } else {
                    p0x = fmaxf(p0x, 0.f); p0y = fmaxf(p0y, 0.f);
                    p1x = fmaxf(p1x, 0.f); p1y = fmaxf(p1y, 0.f);
                    int ch = c - 128;
                    if (r0 < M) { __half2 v = __floats2half2_rn(p0x, p0y);
                                  *(__half2*)(hm + (size_t)r0 * 64 + ch) = v; }
                    if (r1 < M) { __half2 v = __floats2half2_rn(p1x, p1y);
                                  *(__half2*)(hm + (size_t)r1 * 64 + ch) = v; }
                }
            }
        }
        __syncthreads();
    }
}

// ------ layer-1 attention combine + relu -> fea16 --------------------------

__global__ __launch_bounds__(256)
void att_fuse(const __half* __restrict__ ol, const __half* __restrict__ oh,
              const __half* __restrict__ om,
              const float* __restrict__ vl, const float* __restrict__ vh,
              const float* __restrict__ vm, const float* __restrict__ av,
              __half* __restrict__ fea16, int n) {
    int gw = (blockIdx.x * blockDim.x + threadIdx.x) >> 5;
    if (gw >= n) return;
    const int lane = threadIdx.x & 31;
    const size_t base = (size_t)gw * 128 + lane * 4;

    uint2 lv = *(const uint2*)(ol + base);
    uint2 hv = *(const uint2*)(oh + base);
    uint2 mv = *(const uint2*)(om + base);
    float2 l01 = __half22float2(*(__half2*)&lv.x), l23 = __half22float2(*(__half2*)&lv.y);
    float2 h01 = __half22float2(*(__half2*)&hv.x), h23 = __half22float2(*(__half2*)&hv.y);
    float2 m01 = __half22float2(*(__half2*)&mv.x), m23 = __half22float2(*(__half2*)&mv.y);
    float low[4] = {l01.x, l01.y, l23.x, l23.y};
    float high[4] = {h01.x, h01.y, h23.x, h23.y};
    float mlp[4] = {m01.x, m01.y, m23.x, m23.y};

    float dl = 0.f, dh = 0.f, dm = 0.f;
    #pragma unroll
    for (int i = 0; i < 4; i++) {
        dl += low[i]  * vl[lane * 4 + i];
        dh += high[i] * vh[lane * 4 + i];
        dm += mlp[i]  * vm[lane * 4 + i];
    }
    #pragma unroll
    for (int o = 16; o > 0; o >>= 1) {
        dl += __shfl_xor_sync(0xffffffffu, dl, o);
        dh += __shfl_xor_sync(0xffffffffu, dh, o);
        dm += __shfl_xor_sync(0xffffffffu, dm, o);
    }

    float sl = 1.0f / (1.0f + __expf(-dl));
    float sh = 1.0f / (1.0f + __expf(-dh));
    float sm = 1.0f / (1.0f + __expf(-dm));

    float t0 = (sl * av[0] + sh * av[3] + sm * av[6]) * (1.0f / 3.0f);
    float t1 = (sl * av[1] + sh * av[4] + sm * av[7]) * (1.0f / 3.0f);
    float t2 = (sl * av[2] + sh * av[5] + sm * av[8]) * (1.0f / 3.0f);
    float mx = fmaxf(t0, fmaxf(t1, t2));
    float w0 = __expf(t0 - mx), w1 = __expf(t1 - mx), w2 = __expf(t2 - mx);
    float wsum = w0 + w1 + w2;
    float a0 = 3.0f * w0 / wsum, a1 = 3.0f * w1 / wsum, a2 = 3.0f * w2 / wsum;

    float tmp[4];
    #pragma unroll
    for (int i = 0; i < 4; i++)
        tmp[i] = fmaxf(a0 * low[i] + a1 * high[i] + a2 * mlp[i], 0.f);

    __half2 p0 = __floats2half2_rn(tmp[0], tmp[1]);
    __half2 p1 = __floats2half2_rn(tmp[2], tmp[3]);
    uint2 o;
    o.x = *(uint32_t*)&p0; o.y = *(uint32_t*)&p1;
    ((uint2*)fea16)[base / 4] = o;
}

// ---- layer-2 fused spmm + attention (fp16 gather, unroll8) ----------------

__global__ __launch_bounds__(256)
void acm_fuse64(const __half* __restrict__ hlh16, const __half* __restrict__ hm16,
                const int* __restrict__ rowptr, const int* __restrict__ col,
                const float* __restrict__ vl, const float* __restrict__ vh,
                const float* __restrict__ vm, const float* __restrict__ av,
                float* __restrict__ out, int n) {
    int gw = (blockIdx.x * blockDim.x + threadIdx.x) >> 5;
    if (gw >= n) return;
    const int lane = threadIdx.x & 31;
    const int s = rowptr[gw], e = rowptr[gw + 1];
    const bool hiHalf = lane >= 16;

    float acc[4] = {0.f, 0.f, 0.f, 0.f};

    for (int base = s; base < e; base += 32) {
        int idx = base + lane;
        int c = (idx < e) ? col[idx] : 0;
        int cnt = min(32, e - base);
        int k = 0;
        for (; k + 8 <= cnt; k += 8) {
            uint2 v[8];
            #pragma unroll
            for (int j = 0; j < 8; j++) {
                int cc = __shfl_sync(0xffffffffu, c, k + j);
                v[j] = __ldg((const uint2*)(hlh16 + (size_t)cc * 128 + lane * 4));
            }
            #pragma unroll
            for (int j = 0; j < 8; j++) {
                float2 a = __half22float2(*(__half2*)&v[j].x);
                float2 b = __half22float2(*(__half2*)&v[j].y);
                acc[0] += a.x; acc[1] += a.y; acc[2] += b.x; acc[3] += b.y;
            }
        }
        for (; k < cnt; k++) {
            int cc = __shfl_sync(0xffffffffu, c, k);
            uint2 v = __ldg((const uint2*)(hlh16 + (size_t)cc * 128 + lane * 4));
            float2 a = __half22float2(*(__half2*)&v.x);
            float2 b = __half22float2(*(__half2*)&v.y);
            acc[0] += a.x; acc[1] += a.y; acc[2] += b.x; acc[3] += b.y;
        }
    }

    const float inv = (e > s) ? 1.0f / (float)(e - s) : 0.0f;

    uint2 ov = *(const uint2*)(hlh16 + (size_t)gw * 128 + lane * 4);
    float2 o01 = __half22float2(*(__half2*)&ov.x);
    float2 o23 = __half22float2(*(__half2*)&ov.y);
    float own[4] = {o01.x, o01.y, o23.x, o23.y};

    uint2 mv = *(const uint2*)(hm16 + (size_t)gw * 64 + (lane & 15) * 4);
    float2 m01 = __half22float2(*(__half2*)&mv.x);
    float2 m23 = __half22float2(*(__half2*)&mv.y);
    float mlp[4] = {m01.x, m01.y, m23.x, m23.y};

    float val[4];
    #pragma unroll
    for (int j = 0; j < 4; j++) {
        float a = inv * acc[j];
        val[j] = hiHalf ? fmaxf(own[j] - a, 0.f) : fmaxf(a, 0.f);
    }

    float dl = 0.f, dh = 0.f, dm = 0.f;
    if (!hiHalf) {
        #pragma unroll
        for (int j = 0; j < 4; j++) {
            dl += val[j] * vl[lane * 4 + j];
            dm += mlp[j] * vm[lane * 4 + j];
        }
    } else {
        #pragma unroll
        for (int j = 0; j < 4; j++)
            dh += val[j] * vh[(lane - 16) * 4 + j];
    }
    #pragma unroll
    for (int o = 16; o > 0; o >>= 1) {
        dl += __shfl_xor_sync(0xffffffffu, dl, o);
        dh += __shfl_xor_sync(0xffffffffu, dh, o);
        dm += __shfl_xor_sync(0xffffffffu, dm, o);
    }

    float sl = 1.0f / (1.0f + __expf(-dl));
    float sh = 1.0f / (1.0f + __expf(-dh));
    float sm = 1.0f / (1.0f + __expf(-dm));

    float t0 = (sl * av[0] + sh * av[3] + sm * av[6]) * (1.0f / 3.0f);
    float t1 = (sl * av[1] + sh * av[4] + sm * av[7]) * (1.0f / 3.0f);
    float t2 = (sl * av[2] + sh * av[5] + sm * av[8]) * (1.0f / 3.0f);
    float mx = fmaxf(t0, fmaxf(t1, t2));
    float w0 = __expf(t0 - mx), w1 = __expf(t1 - mx), w2 = __expf(t2 - mx);
    float wsum = w0 + w1 + w2;
    float a0 = 3.0f * w0 / wsum, a1 = 3.0f * w1 / wsum, a2 = 3.0f * w2 / wsum;

    float part[4], other[4];
    #pragma unroll
    for (int j = 0; j < 4; j++)
        part[j] = hiHalf ? a1 * val[j] : a0 * val[j];
    #pragma unroll
    for (int j = 0; j < 4; j++)
        other[j] = __shfl_xor_sync(0xffffffffu, part[j], 16);

    if (!hiHalf) {
        float4 o4;
        o4.x = part[0] + other[0] + a2 * mlp[0];
        o4.y = part[1] + other[1] + a2 * mlp[1];
        o4.z = part[2] + other[2] + a2 * mlp[2];
        o4.w = part[3] + other[3] + a2 * mlp[3];
        *(float4*)(out + (size_t)gw * 64 + lane * 4) = o4;
    }
}

// ------------------------------ launch -------------------------------------

extern "C" void kernel_launch(void* const* d_in, const int* in_sizes, int n_in,
                              void* d_out, int out_size) {
    const float* x    = (const float*)d_in[0];
    const int*   ei   = (const int*)d_in[1];
    const float* Wl1  = (const float*)d_in[2];
    const float* Wh1  = (const float*)d_in[3];
    const float* Wm1  = (const float*)d_in[4];
    const float* vl1  = (const float*)d_in[5];
    const float* vh1  = (const float*)d_in[6];
    const float* vm1  = (const float*)d_in[7];
    const float* av1  = (const float*)d_in[8];
    const float* Wl2  = (const float*)d_in[9];
    const float* Wh2  = (const float*)d_in[10];
    const float* Wm2  = (const float*)d_in[11];
    const float* vl2  = (const float*)d_in[12];
    const float* vh2  = (const float*)d_in[13];
    const float* vm2  = (const float*)d_in[14];
    const float* av2  = (const float*)d_in[15];

    const int n = in_sizes[0] / 128;
    const int E = in_sizes[1] / 2;
    const int* row = ei;
    const int* colsrc = ei + E;

    int *deg, *rowptr, *col, *bsum, *boff;
    unsigned short* ticket;
    __half *x16, *agg16, *dif16, *hl16, *hh16, *hmm16, *fea16, *lh16, *hm16;
    __half *w1hi, *w1lo, *w2hi, *w2lo;
    cudaGetSymbolAddress((void**)&deg, g_deg);
    cudaGetSymbolAddress((void**)&rowptr, g_rowptr);
    cudaGetSymbolAddress((void**)&col, g_col);
    cudaGetSymbolAddress((void**)&bsum, g_bsum);
    cudaGetSymbolAddress((void**)&boff, g_boff);
    cudaGetSymbolAddress((void**)&ticket, g_ticket);
    cudaGetSymbolAddress((void**)&x16, g_x16);
    cudaGetSymbolAddress((void**)&agg16, g_agg16);
    cudaGetSymbolAddress((void**)&dif16, g_dif16);
    cudaGetSymbolAddress((void**)&hl16, g_hl16);
    cudaGetSymbolAddress((void**)&hh16, g_hh16);
    cudaGetSymbolAddress((void**)&hmm16, g_hmm16);
    cudaGetSymbolAddress((void**)&fea16, g_fea16);
    cudaGetSymbolAddress((void**)&lh16, g_lh16);
    cudaGetSymbolAddress((void**)&hm16, g_hm16);
    cudaGetSymbolAddress((void**)&w1hi, g_w1hi);
    cudaGetSymbolAddress((void**)&w1lo, g_w1lo);
    cudaGetSymbolAddress((void**)&w2hi, g_w2hi);
    cudaGetSymbolAddress((void**)&w2lo, g_w2lo);

    float* out = (float*)d_out;

    const int SA = 136;
    const int smem1 = (2 * 128 * SA + 2 * 128 * SA) * 2;
    const int smem2 = (2 * 128 * SA + 2 * 192 * SA) * 2;
    cudaFuncSetAttribute(gemm_l1, cudaFuncAttributeMaxDynamicSharedMemorySize, smem1);
    cudaFuncSetAttribute(gemm_l2, cudaFuncAttributeMaxDynamicSharedMemorySize, smem2);

    const int nblk = (n + 1023) / 1024;   // <= NBLK

    zero_kernel<<<(n + 255) / 256, 256>>>(deg, n);
    {
        int tot = E + n * 32 + 3 * 128 * 128 + 3 * 64 * 128;
        work_kernel<<<(tot + 255) / 256, 256>>>(row, deg, ticket, E, x, x16,
                                                Wl1, Wh1, Wm1, w1hi, w1lo,
                                                Wl2, Wh2, Wm2, w2hi, w2lo, n);
    }
    scanA_kernel<<<nblk, 1024>>>(deg, rowptr, bsum, n);
    scanB_kernel<<<1, NBLK>>>(bsum, boff, rowptr, nblk, n);
    scanC_kernel<<<(n + 255) / 256, 256>>>(rowptr, boff, n);
    scatter_kernel<<<(E + 255) / 256, 256>>>(row, colsrc, rowptr, ticket, col, E);

    const int gx4 = (n + 511) / 512;
    const int gx2 = (n + 255) / 256;

    spmm_cvt<<<(n + 7) / 8, 256>>>(x16, rowptr, col, agg16, dif16, n);
    {
        dim3 grid(gx4, 3);
        gemm_l1<<<grid, 256, smem1>>>(agg16, dif16, x16, w1hi, w1lo, hl16, hh16, hmm16, n);
    }
    att_fuse<<<(n + 7) / 8, 256>>>(hl16, hh16, hmm16, vl1, vh1, vm1, av1, fea16, n);

    gemm_l2<<<gx2, 256, smem2>>>(fea16, w2hi, w2lo, lh16, hm16, n);
    acm_fuse64<<<(n + 7) / 8, 256>>>(lh16, hm16, rowptr, col,
                                     vl2, vh2, vm2, av2, out, n);
}